// round 1
// baseline (speedup 1.0000x reference)
#include <cuda_runtime.h>
#include <cuda_bf16.h>
#include <math.h>

#define G 3072
#define P 1024
#define ALPHA 0.1f

// Scratch (device globals — no allocation allowed in kernel_launch)
__device__ float g_Asc[(size_t)G * G];  // alpha * softmax(scores)
__device__ float g_Sa [(size_t)G * G];  // Neumann partial sum ping
__device__ float g_Sb [(size_t)G * G];  // Neumann partial sum pong

// ---------------------------------------------------------------------------
// Kernel 1: row softmax of g_g_score[:, :, 1] with -inf diagonal.
// Writes Asc = ALPHA * softmax (diagonal = 0). One block per row.
// ---------------------------------------------------------------------------
__global__ void softmax_rows_kernel(const float* __restrict__ gg,
                                    float* __restrict__ Asc) {
    const int i   = blockIdx.x;
    const int tid = threadIdx.x;
    const float* base = gg + (size_t)i * (2 * G) + 1;  // channel 1, stride 2

    __shared__ float red[256];

    // pass 1: max over off-diagonal
    float m = -1e30f;
    for (int j = tid; j < G; j += 256)
        if (j != i) m = fmaxf(m, base[2 * j]);
    red[tid] = m;
    __syncthreads();
    for (int s = 128; s > 0; s >>= 1) {
        if (tid < s) red[tid] = fmaxf(red[tid], red[tid + s]);
        __syncthreads();
    }
    const float mx = red[0];
    __syncthreads();

    // pass 2: sum of exp
    float sum = 0.0f;
    for (int j = tid; j < G; j += 256)
        if (j != i) sum += expf(base[2 * j] - mx);
    red[tid] = sum;
    __syncthreads();
    for (int s = 128; s > 0; s >>= 1) {
        if (tid < s) red[tid] += red[tid + s];
        __syncthreads();
    }
    const float inv = ALPHA / red[0];

    // pass 3: write alpha * softmax, 0 on diagonal
    for (int j = tid; j < G; j += 256)
        Asc[(size_t)i * G + j] = (j == i) ? 0.0f : expf(base[2 * j] - mx) * inv;
}

// ---------------------------------------------------------------------------
// Kernel 2: S = I + Asc  (first Neumann term). Grid-stride elementwise.
// ---------------------------------------------------------------------------
__global__ void init_S_kernel(const float* __restrict__ Asc,
                              float* __restrict__ S) {
    const size_t total = (size_t)G * G;
    for (size_t idx = (size_t)blockIdx.x * blockDim.x + threadIdx.x;
         idx < total; idx += (size_t)gridDim.x * blockDim.x) {
        const int r = (int)(idx / G);
        const int c = (int)(idx % G);
        S[idx] = Asc[idx] + (r == c ? 1.0f : 0.0f);
    }
}

// ---------------------------------------------------------------------------
// Kernel 3: Horner step  C = Asc * B + I   (all G x G, row-major, fp32)
// 128x128x16 tile, 256 threads, 8x8 per thread.
// ---------------------------------------------------------------------------
__global__ __launch_bounds__(256, 2)
void horner_gemm(const float* __restrict__ A, const float* __restrict__ B,
                 float* __restrict__ C) {
    __shared__ float As[16][132];  // padded: transpose-store conflicts -> 2-way
    __shared__ float Bs[16][128];

    const int tid  = threadIdx.x;
    const int tx   = tid % 16;
    const int ty   = tid / 16;
    const int row0 = blockIdx.y * 128;
    const int col0 = blockIdx.x * 128;

    const float* Aptr = A + (size_t)row0 * G;
    const float* Bptr = B + col0;

    float acc[8][8] = {};

    for (int k0 = 0; k0 < G; k0 += 16) {
        // load A tile [128 rows][16 k], store transposed As[k][row]
#pragma unroll
        for (int l = 0; l < 2; l++) {
            const int q  = tid + l * 256;          // float4 id, 512 total
            const int r  = q >> 2;                  // row in tile
            const int c4 = (q & 3) * 4;             // k offset
            float4 v = *reinterpret_cast<const float4*>(Aptr + (size_t)r * G + k0 + c4);
            As[c4 + 0][r] = v.x; As[c4 + 1][r] = v.y;
            As[c4 + 2][r] = v.z; As[c4 + 3][r] = v.w;
        }
        // load B tile [16 k][128 cols], row-major, float4
#pragma unroll
        for (int l = 0; l < 2; l++) {
            const int q  = tid + l * 256;
            const int kk = q >> 5;
            const int j4 = (q & 31) * 4;
            float4 v = *reinterpret_cast<const float4*>(Bptr + (size_t)(k0 + kk) * G + j4);
            *reinterpret_cast<float4*>(&Bs[kk][j4]) = v;
        }
        __syncthreads();

#pragma unroll
        for (int kk = 0; kk < 16; kk++) {
            float a[8], b[8];
            *reinterpret_cast<float4*>(&a[0]) = *reinterpret_cast<const float4*>(&As[kk][ty * 8 + 0]);
            *reinterpret_cast<float4*>(&a[4]) = *reinterpret_cast<const float4*>(&As[kk][ty * 8 + 4]);
            *reinterpret_cast<float4*>(&b[0]) = *reinterpret_cast<const float4*>(&Bs[kk][tx * 8 + 0]);
            *reinterpret_cast<float4*>(&b[4]) = *reinterpret_cast<const float4*>(&Bs[kk][tx * 8 + 4]);
#pragma unroll
            for (int i = 0; i < 8; i++)
#pragma unroll
                for (int j = 0; j < 8; j++)
                    acc[i][j] = fmaf(a[i], b[j], acc[i][j]);
        }
        __syncthreads();
    }

    // write C = acc + I
#pragma unroll
    for (int i = 0; i < 8; i++) {
        const int r = row0 + ty * 8 + i;
#pragma unroll
        for (int j = 0; j < 8; j++) {
            const int cidx = col0 + tx * 8 + j;
            if (r == cidx) acc[i][j] += 1.0f;
        }
        float* crow = C + (size_t)r * G + col0 + tx * 8;
        *reinterpret_cast<float4*>(crow + 0) = make_float4(acc[i][0], acc[i][1], acc[i][2], acc[i][3]);
        *reinterpret_cast<float4*>(crow + 4) = make_float4(acc[i][4], acc[i][5], acc[i][6], acc[i][7]);
    }
}

// ---------------------------------------------------------------------------
// Kernel 4: final propagate for one channel c:
//   out[(i*G + j)*2 + c] = (1-ALPHA) * sum_k X[i,k,c] * S[j,k]
// X rows: i < P -> p_g_score, else g_g_score (global row order == concat order).
// Both operands K-major ("TN" GEMM). 128x128x16, 256 threads, 8x8/thread.
// ---------------------------------------------------------------------------
__global__ __launch_bounds__(256, 2)
void final_gemm(const float* __restrict__ pgin, const float* __restrict__ ggin,
                const float* __restrict__ S, float* __restrict__ out,
                const int c) {
    __shared__ float Xs[16][132];  // padded
    __shared__ float Ss[16][132];  // padded

    const int tid  = threadIdx.x;
    const int tx   = tid % 16;
    const int ty   = tid / 16;
    const int row0 = blockIdx.y * 128;   // M dim (P+G = 4096)
    const int col0 = blockIdx.x * 128;   // N dim (G)

    // P = 1024 is a multiple of 128: whole block is in one source tensor
    const float* src;
    size_t base_row;
    if (row0 < P) { src = pgin; base_row = (size_t)row0; }
    else          { src = ggin; base_row = (size_t)(row0 - P); }

    float acc[8][8] = {};

    for (int k0 = 0; k0 < G; k0 += 16) {
        // X tile: [128 rows][16 k], element stride 2 (interleaved channels)
#pragma unroll
        for (int l = 0; l < 8; l++) {
            const int q  = tid + l * 256;   // 2048 scalars
            const int r  = q >> 4;
            const int kk = q & 15;
            Xs[kk][r] = src[((base_row + r) * G + (k0 + kk)) * 2 + c];
        }
        // S tile: rows j = col0..col0+127, k-contiguous, transpose into Ss[k][j]
#pragma unroll
        for (int l = 0; l < 2; l++) {
            const int q  = tid + l * 256;
            const int j  = q >> 2;
            const int k4 = (q & 3) * 4;
            float4 v = *reinterpret_cast<const float4*>(S + (size_t)(col0 + j) * G + k0 + k4);
            Ss[k4 + 0][j] = v.x; Ss[k4 + 1][j] = v.y;
            Ss[k4 + 2][j] = v.z; Ss[k4 + 3][j] = v.w;
        }
        __syncthreads();

#pragma unroll
        for (int kk = 0; kk < 16; kk++) {
            float a[8], b[8];
            *reinterpret_cast<float4*>(&a[0]) = *reinterpret_cast<const float4*>(&Xs[kk][ty * 8 + 0]);
            *reinterpret_cast<float4*>(&a[4]) = *reinterpret_cast<const float4*>(&Xs[kk][ty * 8 + 4]);
            *reinterpret_cast<float4*>(&b[0]) = *reinterpret_cast<const float4*>(&Ss[kk][tx * 8 + 0]);
            *reinterpret_cast<float4*>(&b[4]) = *reinterpret_cast<const float4*>(&Ss[kk][tx * 8 + 4]);
#pragma unroll
            for (int i = 0; i < 8; i++)
#pragma unroll
                for (int j = 0; j < 8; j++)
                    acc[i][j] = fmaf(a[i], b[j], acc[i][j]);
        }
        __syncthreads();
    }

    const float scale = 1.0f - ALPHA;
#pragma unroll
    for (int i = 0; i < 8; i++) {
        const size_t gi = (size_t)(row0 + ty * 8 + i);
#pragma unroll
        for (int j = 0; j < 8; j++) {
            const size_t gj = (size_t)(col0 + tx * 8 + j);
            out[(gi * G + gj) * 2 + c] = scale * acc[i][j];
        }
    }
}

// ---------------------------------------------------------------------------
extern "C" void kernel_launch(void* const* d_in, const int* in_sizes, int n_in,
                              void* d_out, int out_size) {
    const float* pg = (const float*)d_in[0];
    const float* gg = (const float*)d_in[1];
    // defensive: identify tensors by size (p_g: P*G*2, g_g: G*G*2)
    if (in_sizes[0] == G * G * 2) { const float* t = pg; pg = gg; gg = t; }

    float *Asc, *Sa, *Sb;
    cudaGetSymbolAddress((void**)&Asc, g_Asc);
    cudaGetSymbolAddress((void**)&Sa,  g_Sa);
    cudaGetSymbolAddress((void**)&Sb,  g_Sb);
    float* out = (float*)d_out;

    // 1. A_scaled = alpha * softmax(scores with -inf diag)
    softmax_rows_kernel<<<G, 256>>>(gg, Asc);

    // 2. S1 = I + alpha*A
    init_S_kernel<<<1184, 256>>>(Asc, Sa);

    // 3. Horner: S_{k+1} = I + (alpha*A) * S_k   -> S5 ends in Sa
    dim3 gh(G / 128, G / 128);
    horner_gemm<<<gh, 256>>>(Asc, Sa, Sb);
    horner_gemm<<<gh, 256>>>(Asc, Sb, Sa);
    horner_gemm<<<gh, 256>>>(Asc, Sa, Sb);
    horner_gemm<<<gh, 256>>>(Asc, Sb, Sa);

    // 4. out = (1-alpha) * X @ S^T, channels interleaved, pg rows then gg rows
    dim3 gf(G / 128, (P + G) / 128);
    final_gemm<<<gf, 256>>>(pg, gg, Sa, out, 0);
    final_gemm<<<gf, 256>>>(pg, gg, Sa, out, 1);
}

// round 3
// speedup vs baseline: 5.1901x; 5.1901x over previous
#include <cuda_runtime.h>
#include <cuda_bf16.h>
#include <math.h>
#include <stdint.h>

#define G 3072
#define P 1024
#define PG 4096          // rows per channel of X
#define M2 8192          // 2 channels stacked
#define ALPHA 0.1f

// ---------------- scratch (device globals; no allocation in kernel_launch) --
__device__ float g_Asc [(size_t)G * G];   // alpha * softmax(scores), row-major
__device__ float g_AscT[(size_t)G * G];   // transpose of Asc (= W1)
__device__ float g_Wa  [(size_t)G * G];
__device__ float g_Wb  [(size_t)G * G];
__device__ float g_R   [(size_t)G * G];   // R = W_final^T
__device__ float g_X2  [(size_t)M2 * G];  // deinterleaved X: ch0 rows, then ch1

// ---------------- PTX helpers (all generic sm_100 compatible) ---------------
__device__ __forceinline__ uint32_t smem_u32(const void* p) {
    uint32_t a;
    asm("{ .reg .u64 t; cvta.to.shared.u64 t, %1; cvt.u32.u64 %0, t; }"
        : "=r"(a) : "l"(p));
    return a;
}
__device__ __forceinline__ void cp_async16(uint32_t dst, const void* src) {
    asm volatile("cp.async.cg.shared.global [%0], [%1], 16;" :: "r"(dst), "l"(src));
}
#define CP_COMMIT() asm volatile("cp.async.commit_group;" ::: "memory")
#define CP_WAIT(n)  asm volatile("cp.async.wait_group %0;" :: "n"(n) : "memory")

__device__ __forceinline__ void ldsm_x4(uint32_t* r, uint32_t addr) {
    asm volatile("ldmatrix.sync.aligned.m8n8.x4.shared.b16 {%0,%1,%2,%3}, [%4];"
                 : "=r"(r[0]), "=r"(r[1]), "=r"(r[2]), "=r"(r[3]) : "r"(addr));
}
__device__ __forceinline__ void mma_tf32(float* c, const uint32_t* a, const uint32_t* b) {
    asm volatile(
        "mma.sync.aligned.m16n8k8.row.col.f32.tf32.tf32.f32 "
        "{%0,%1,%2,%3}, {%4,%5,%6,%7}, {%8,%9}, {%0,%1,%2,%3};"
        : "+f"(c[0]), "+f"(c[1]), "+f"(c[2]), "+f"(c[3])
        : "r"(a[0]), "r"(a[1]), "r"(a[2]), "r"(a[3]), "r"(b[0]), "r"(b[1]));
}

// ---------------- GEMM: D[128x128] = A[128,K] . B[128,K]^T ------------------
//   MODE 0: Cout = D + Add                              (Horner step)
//   MODE 1: out[(ii*G+col)*2+c] = 0.9*(Add + D)          (final, interleave)
#define TM 128
#define TN 128
#define KCH 32
#define STAGES 3
#define ATILE_B (TM * KCH * 4)              // 16384
#define STAGE_BYTES (2 * ATILE_B)           // 32768
#define NCHUNK (G / KCH)                    // 96
#define SMEM_DYN (STAGES * STAGE_BYTES)     // 98304

template <int MODE>
__global__ __launch_bounds__(256, 2)
void gemm_mma(const float* __restrict__ Aop, const float* __restrict__ Bop,
              const float* __restrict__ Add, float* __restrict__ Cout) {
    extern __shared__ char smem_raw[];
    const uint32_t sbase = smem_u32(smem_raw);

    const int tid  = threadIdx.x;
    const int lane = tid & 31;
    const int wid  = tid >> 5;
    const int wm   = wid & 3;        // 4 warps along M -> 32 rows each
    const int wn   = wid >> 2;       // 2 warps along N -> 64 cols each
    const int row0 = blockIdx.y * TM;
    const int col0 = blockIdx.x * TN;

    const float* arow = Aop + (size_t)row0 * G;
    const float* brow = Bop + (size_t)col0 * G;

    // cp.async store pattern (per thread, 4 float4 per operand tile)
    // smem layout per tile: [128 rows][32 f32] = 128B rows, SW128 swizzle:
    //   off(r, byte) = r*128 + (byte ^ ((r&7)<<4))
    // ldmatrix read offsets (A fragment, m16n8k8 tf32):
    const int ar    = lane & 15;                 // row within m16 tile
    const int abyte = (lane >> 4) << 4;          // 0 or 16
    const uint32_t amask = (uint32_t)((ar & 7) << 4);
    const uint32_t aoff0 = (uint32_t)((wm * 32 + ar) * 128);
    const uint32_t aoff1 = aoff0 + 16 * 128;
    // B fragment rows (two n8 tiles per x4)
    const int brl   = (lane & 7) | (((lane >> 4) & 1) << 3);
    const int bbyte = ((lane >> 3) & 1) << 4;
    const uint32_t bmask = (uint32_t)((lane & 7) << 4);
    uint32_t boff[4];
#pragma unroll
    for (int ntp = 0; ntp < 4; ntp++)
        boff[ntp] = (uint32_t)((wn * 64 + ntp * 16 + brl) * 128);

    float acc[2][8][4] = {};

    // ---- stage loader ----
    auto load_stage = [&](int stage, int k0) {
        const uint32_t sA = sbase + stage * STAGE_BYTES;
        const uint32_t sB = sA + ATILE_B;
#pragma unroll
        for (int l = 0; l < 4; l++) {
            const int q = tid + (l << 8);
            const int r = q >> 3, sg = q & 7;
            cp_async16(sA + (uint32_t)(r * 128 + ((sg * 16) ^ ((r & 7) << 4))),
                       arow + (size_t)r * G + k0 + sg * 4);
        }
#pragma unroll
        for (int l = 0; l < 4; l++) {
            const int q = tid + (l << 8);
            const int r = q >> 3, sg = q & 7;
            cp_async16(sB + (uint32_t)(r * 128 + ((sg * 16) ^ ((r & 7) << 4))),
                       brow + (size_t)r * G + k0 + sg * 4);
        }
        CP_COMMIT();
    };

    // prologue: stages 0..STAGES-2
    load_stage(0, 0);
    load_stage(1, KCH);

    for (int ch = 0; ch < NCHUNK; ch++) {
        CP_WAIT(STAGES - 2);
        __syncthreads();

        if (ch + STAGES - 1 < NCHUNK)
            load_stage((ch + STAGES - 1) % STAGES, (ch + STAGES - 1) * KCH);
        else
            CP_COMMIT();   // empty group keeps wait_group accounting uniform

        const uint32_t sA = sbase + (ch % STAGES) * STAGE_BYTES;
        const uint32_t sB = sA + ATILE_B;
#pragma unroll
        for (int ks = 0; ks < 4; ks++) {
            const uint32_t kb = (uint32_t)(ks * 32);
            uint32_t a0[4], a1[4];
            ldsm_x4(a0, sA + aoff0 + ((kb + abyte) ^ amask));
            ldsm_x4(a1, sA + aoff1 + ((kb + abyte) ^ amask));
            uint32_t b[4][4];
#pragma unroll
            for (int ntp = 0; ntp < 4; ntp++)
                ldsm_x4(b[ntp], sB + boff[ntp] + ((kb + bbyte) ^ bmask));
#pragma unroll
            for (int nt = 0; nt < 8; nt++) {
                const uint32_t* bp = &b[nt >> 1][(nt & 1) * 2];
                mma_tf32(acc[0][nt], a0, bp);
                mma_tf32(acc[1][nt], a1, bp);
            }
        }
        __syncthreads();
    }

    // ---------------- epilogue ------------------------------------------------
    const int rbase = lane >> 2;            // 0..7
    const int cbase = (lane & 3) * 2;       // 0,2,4,6
#pragma unroll
    for (int mt = 0; mt < 2; mt++) {
#pragma unroll
        for (int nt = 0; nt < 8; nt++) {
            const int grow = row0 + wm * 32 + mt * 16 + rbase;
            const int gcol = col0 + wn * 64 + nt * 8 + cbase;
#pragma unroll
            for (int h = 0; h < 2; h++) {     // h=0 -> rows r, h=1 -> r+8
                const int gr = grow + h * 8;
                const float v0 = acc[mt][nt][h * 2 + 0];
                const float v1 = acc[mt][nt][h * 2 + 1];
                if (MODE == 0) {
                    const size_t i0 = (size_t)gr * G + gcol;
                    float2 ad = *reinterpret_cast<const float2*>(Add + i0);
                    float2 o;
                    o.x = v0 + ad.x;
                    o.y = v1 + ad.y;
                    *reinterpret_cast<float2*>(Cout + i0) = o;
                } else {
                    const int c  = gr >> 12;           // channel
                    const int ii = gr & (PG - 1);
                    float2 x = *reinterpret_cast<const float2*>(
                        Add + (size_t)gr * G + gcol);
                    float* ob = Cout + ((size_t)ii * G + gcol) * 2 + c;
                    ob[0] = 0.9f * (x.x + v0);
                    ob[2] = 0.9f * (x.y + v1);
                }
            }
        }
    }
}

// ---------------- softmax: Asc = alpha * softmax(gg[:,:,1], -inf diag) -----
__global__ void softmax_rows_kernel(const float* __restrict__ gg,
                                    float* __restrict__ Asc) {
    const int i   = blockIdx.x;
    const int tid = threadIdx.x;
    const float* base = gg + (size_t)i * (2 * G) + 1;

    __shared__ float rowv[G];
    __shared__ float red[256];

    for (int j = tid; j < G; j += 256)
        rowv[j] = (j == i) ? -1e30f : base[2 * j];
    __syncthreads();

    float m = -1e30f;
    for (int j = tid; j < G; j += 256) m = fmaxf(m, rowv[j]);
    red[tid] = m;
    __syncthreads();
    for (int s = 128; s > 0; s >>= 1) {
        if (tid < s) red[tid] = fmaxf(red[tid], red[tid + s]);
        __syncthreads();
    }
    const float mx = red[0];
    __syncthreads();

    float sum = 0.0f;
    for (int j = tid; j < G; j += 256) {
        const float e = expf(rowv[j] - mx);
        rowv[j] = e;
        sum += e;
    }
    red[tid] = sum;
    __syncthreads();
    for (int s = 128; s > 0; s >>= 1) {
        if (tid < s) red[tid] += red[tid + s];
        __syncthreads();
    }
    const float inv = ALPHA / red[0];
    __syncthreads();

    for (int j = tid; j < G; j += 256)
        Asc[(size_t)i * G + j] = rowv[j] * inv;
}

// ---------------- transpose G x G -------------------------------------------
__global__ void transpose_k(const float* __restrict__ in, float* __restrict__ out) {
    __shared__ float t[32][33];
    const int x  = blockIdx.x * 32 + threadIdx.x;
    const int y0 = blockIdx.y * 32;
#pragma unroll
    for (int dy = 0; dy < 32; dy += 8)
        t[threadIdx.y + dy][threadIdx.x] = in[(size_t)(y0 + threadIdx.y + dy) * G + x];
    __syncthreads();
    const int ox = y0 + threadIdx.x;
#pragma unroll
    for (int dy = 0; dy < 32; dy += 8)
        out[(size_t)(blockIdx.x * 32 + threadIdx.y + dy) * G + ox] =
            t[threadIdx.x][threadIdx.y + dy];
}

// ---------------- deinterleave X channels -----------------------------------
__global__ void deinterleave_kernel(const float* __restrict__ pg,
                                    const float* __restrict__ gg,
                                    float* __restrict__ X2) {
    const size_t total = (size_t)PG * G;
    for (size_t idx = (size_t)blockIdx.x * blockDim.x + threadIdx.x;
         idx < total; idx += (size_t)gridDim.x * blockDim.x) {
        const int i = (int)(idx / G);
        const int k = (int)(idx % G);
        const float* src = (i < P) ? (pg + ((size_t)i * G + k) * 2)
                                   : (gg + ((size_t)(i - P) * G + k) * 2);
        float2 v = *reinterpret_cast<const float2*>(src);
        X2[idx] = v.x;
        X2[(size_t)PG * G + idx] = v.y;
    }
}

// ---------------- launcher ---------------------------------------------------
extern "C" void kernel_launch(void* const* d_in, const int* in_sizes, int n_in,
                              void* d_out, int out_size) {
    const float* pg = (const float*)d_in[0];
    const float* gg = (const float*)d_in[1];
    if (in_sizes[0] == G * G * 2) { const float* t = pg; pg = gg; gg = t; }

    float *Asc, *AscT, *Wa, *Wb, *R, *X2;
    cudaGetSymbolAddress((void**)&Asc,  g_Asc);
    cudaGetSymbolAddress((void**)&AscT, g_AscT);
    cudaGetSymbolAddress((void**)&Wa,   g_Wa);
    cudaGetSymbolAddress((void**)&Wb,   g_Wb);
    cudaGetSymbolAddress((void**)&R,    g_R);
    cudaGetSymbolAddress((void**)&X2,   g_X2);
    float* out = (float*)d_out;

    cudaFuncSetAttribute(gemm_mma<0>, cudaFuncAttributeMaxDynamicSharedMemorySize, SMEM_DYN);
    cudaFuncSetAttribute(gemm_mma<1>, cudaFuncAttributeMaxDynamicSharedMemorySize, SMEM_DYN);

    // 1. Asc = alpha*softmax, X2 = deinterleaved inputs, AscT = Asc^T (= W1)
    softmax_rows_kernel<<<G, 256>>>(gg, Asc);
    deinterleave_kernel<<<2048, 256>>>(pg, gg, X2);
    transpose_k<<<dim3(G / 32, G / 32), dim3(32, 8)>>>(Asc, AscT);

    // 2. Horner chain on W = R^T:  W_{k+1} = W_k . Asc^T + AscT  (3 steps)
    dim3 gh(G / TN, G / TM);                        // (24, 24)
    gemm_mma<0><<<gh, 256, SMEM_DYN>>>(AscT, Asc, AscT, Wa);  // W2
    gemm_mma<0><<<gh, 256, SMEM_DYN>>>(Wa,   Asc, AscT, Wb);  // W3
    gemm_mma<0><<<gh, 256, SMEM_DYN>>>(Wb,   Asc, AscT, Wa);  // W4

    // 3. R = W4^T
    transpose_k<<<dim3(G / 32, G / 32), dim3(32, 8)>>>(Wa, R);

    // 4. out = 0.9 * (X + X @ R^T), channels re-interleaved in epilogue
    dim3 gf(G / TN, M2 / TM);                       // (24, 64)
    gemm_mma<1><<<gf, 256, SMEM_DYN>>>(X2, R, X2, out);
}

// round 4
// speedup vs baseline: 6.2294x; 1.2002x over previous
#include <cuda_runtime.h>
#include <cuda_bf16.h>
#include <math.h>
#include <stdint.h>

#define G 3072
#define P 1024
#define PG 4096          // rows per channel of X
#define M2 8192          // 2 channels stacked
#define ALPHA 0.1f

// ---------------- scratch (device globals; no allocation in kernel_launch) --
__device__ float g_Asc [(size_t)G * G];   // alpha * softmax(scores), row-major
__device__ float g_AscT[(size_t)G * G];   // transpose of Asc (= W1)
__device__ float g_Wa  [(size_t)G * G];
__device__ float g_Wb  [(size_t)G * G];
__device__ float g_R   [(size_t)G * G];   // R = W_final^T
__device__ float g_X2  [(size_t)M2 * G];  // deinterleaved X: ch0 rows, then ch1

// ---------------- PTX helpers (all generic sm_100 compatible) ---------------
__device__ __forceinline__ uint32_t smem_u32(const void* p) {
    uint32_t a;
    asm("{ .reg .u64 t; cvta.to.shared.u64 t, %1; cvt.u32.u64 %0, t; }"
        : "=r"(a) : "l"(p));
    return a;
}
__device__ __forceinline__ void cp_async16(uint32_t dst, const void* src) {
    asm volatile("cp.async.cg.shared.global [%0], [%1], 16;" :: "r"(dst), "l"(src));
}
#define CP_COMMIT() asm volatile("cp.async.commit_group;" ::: "memory")
#define CP_WAIT(n)  asm volatile("cp.async.wait_group %0;" :: "n"(n) : "memory")

__device__ __forceinline__ void ldsm_x4(uint32_t* r, uint32_t addr) {
    asm volatile("ldmatrix.sync.aligned.m8n8.x4.shared.b16 {%0,%1,%2,%3}, [%4];"
                 : "=r"(r[0]), "=r"(r[1]), "=r"(r[2]), "=r"(r[3]) : "r"(addr));
}
__device__ __forceinline__ void mma_tf32(float* c, const uint32_t* a, const uint32_t* b) {
    asm volatile(
        "mma.sync.aligned.m16n8k8.row.col.f32.tf32.tf32.f32 "
        "{%0,%1,%2,%3}, {%4,%5,%6,%7}, {%8,%9}, {%0,%1,%2,%3};"
        : "+f"(c[0]), "+f"(c[1]), "+f"(c[2]), "+f"(c[3])
        : "r"(a[0]), "r"(a[1]), "r"(a[2]), "r"(a[3]), "r"(b[0]), "r"(b[1]));
}

// ---------------- GEMM: D[128x128] = A[128,K] . B[128,K]^T ------------------
//   MODE 0: Cout = D + Add                              (Horner step)
//   MODE 1: out[(ii*G+col)*2+c] = 0.9*(Add + D)          (final, interleave)
#define TM 128
#define TN 128
#define KCH 32
#define STAGES 3
#define ATILE_B (TM * KCH * 4)              // 16384
#define STAGE_BYTES (2 * ATILE_B)           // 32768
#define NCHUNK (G / KCH)                    // 96
#define SMEM_DYN (STAGES * STAGE_BYTES)     // 98304

template <int MODE>
__global__ __launch_bounds__(256, 2)
void gemm_mma(const float* __restrict__ Aop, const float* __restrict__ Bop,
              const float* __restrict__ Add, float* __restrict__ Cout) {
    extern __shared__ char smem_raw[];
    const uint32_t sbase = smem_u32(smem_raw);

    const int tid  = threadIdx.x;
    const int lane = tid & 31;
    const int wid  = tid >> 5;
    const int wm   = wid & 3;        // 4 warps along M -> 32 rows each
    const int wn   = wid >> 2;       // 2 warps along N -> 64 cols each
    const int row0 = blockIdx.y * TM;
    const int col0 = blockIdx.x * TN;

    const float* arow = Aop + (size_t)row0 * G;
    const float* brow = Bop + (size_t)col0 * G;

    // smem layout per operand tile: [128 rows][32 f32] = 128B rows, swizzle:
    //   off(r, byte) = r*128 + (byte ^ ((r&7)<<4))
    const int ar    = lane & 15;                 // row within m16 tile
    const int abyte = (lane >> 4) << 4;          // 0 or 16
    const uint32_t amask = (uint32_t)((ar & 7) << 4);
    const uint32_t aoff0 = (uint32_t)((wm * 32 + ar) * 128);
    const uint32_t aoff1 = aoff0 + 16 * 128;
    const int brl   = (lane & 7) | (((lane >> 4) & 1) << 3);
    const int bbyte = ((lane >> 3) & 1) << 4;
    const uint32_t bmask = (uint32_t)((lane & 7) << 4);
    uint32_t boff[4];
#pragma unroll
    for (int ntp = 0; ntp < 4; ntp++)
        boff[ntp] = (uint32_t)((wn * 64 + ntp * 16 + brl) * 128);

    float acc[2][8][4] = {};

    auto load_stage = [&](int stage, int k0) {
        const uint32_t sA = sbase + stage * STAGE_BYTES;
        const uint32_t sB = sA + ATILE_B;
#pragma unroll
        for (int l = 0; l < 4; l++) {
            const int q = tid + (l << 8);
            const int r = q >> 3, sg = q & 7;
            cp_async16(sA + (uint32_t)(r * 128 + ((sg * 16) ^ ((r & 7) << 4))),
                       arow + (size_t)r * G + k0 + sg * 4);
        }
#pragma unroll
        for (int l = 0; l < 4; l++) {
            const int q = tid + (l << 8);
            const int r = q >> 3, sg = q & 7;
            cp_async16(sB + (uint32_t)(r * 128 + ((sg * 16) ^ ((r & 7) << 4))),
                       brow + (size_t)r * G + k0 + sg * 4);
        }
        CP_COMMIT();
    };

    // prologue: STAGES-1 stages in flight
    load_stage(0, 0);
    load_stage(1, KCH);

    for (int ch = 0; ch < NCHUNK; ch++) {
        CP_WAIT(STAGES - 2);
        __syncthreads();
        // Safe to refill slot (ch-1)%STAGES: every thread finished reading it
        // before this barrier (single barrier per iteration, 3-stage ring).
        if (ch + STAGES - 1 < NCHUNK)
            load_stage((ch + STAGES - 1) % STAGES, (ch + STAGES - 1) * KCH);
        else
            CP_COMMIT();   // empty group keeps wait_group accounting uniform

        const uint32_t sA = sbase + (ch % STAGES) * STAGE_BYTES;
        const uint32_t sB = sA + ATILE_B;
#pragma unroll
        for (int ks = 0; ks < 4; ks++) {
            const uint32_t kb = (uint32_t)(ks * 32);
            uint32_t a0[4], a1[4];
            ldsm_x4(a0, sA + aoff0 + ((kb + abyte) ^ amask));
            ldsm_x4(a1, sA + aoff1 + ((kb + abyte) ^ amask));
            uint32_t b[4][4];
#pragma unroll
            for (int ntp = 0; ntp < 4; ntp++)
                ldsm_x4(b[ntp], sB + boff[ntp] + ((kb + bbyte) ^ bmask));
#pragma unroll
            for (int nt = 0; nt < 8; nt++) {
                const uint32_t* bp = &b[nt >> 1][(nt & 1) * 2];
                mma_tf32(acc[0][nt], a0, bp);
                mma_tf32(acc[1][nt], a1, bp);
            }
        }
    }

    // ---------------- epilogue ------------------------------------------------
    const int rbase = lane >> 2;            // 0..7
    const int cbase = (lane & 3) * 2;       // 0,2,4,6
#pragma unroll
    for (int mt = 0; mt < 2; mt++) {
#pragma unroll
        for (int nt = 0; nt < 8; nt++) {
            const int grow = row0 + wm * 32 + mt * 16 + rbase;
            const int gcol = col0 + wn * 64 + nt * 8 + cbase;
#pragma unroll
            for (int h = 0; h < 2; h++) {     // h=0 -> rows r, h=1 -> r+8
                const int gr = grow + h * 8;
                const float v0 = acc[mt][nt][h * 2 + 0];
                const float v1 = acc[mt][nt][h * 2 + 1];
                if (MODE == 0) {
                    const size_t i0 = (size_t)gr * G + gcol;
                    float2 ad = *reinterpret_cast<const float2*>(Add + i0);
                    float2 o;
                    o.x = v0 + ad.x;
                    o.y = v1 + ad.y;
                    *reinterpret_cast<float2*>(Cout + i0) = o;
                } else {
                    const int c  = gr >> 12;           // channel
                    const int ii = gr & (PG - 1);
                    float2 x = *reinterpret_cast<const float2*>(
                        Add + (size_t)gr * G + gcol);
                    float* ob = Cout + ((size_t)ii * G + gcol) * 2 + c;
                    ob[0] = 0.9f * (x.x + v0);
                    ob[2] = 0.9f * (x.y + v1);
                }
            }
        }
    }
}

// ---------------- softmax: Asc = alpha * softmax(gg[:,:,1], -inf diag) -----
__global__ void softmax_rows_kernel(const float* __restrict__ gg,
                                    float* __restrict__ Asc) {
    const int i   = blockIdx.x;
    const int tid = threadIdx.x;
    const float* base = gg + (size_t)i * (2 * G) + 1;

    __shared__ float rowv[G];
    __shared__ float red[256];

    for (int j = tid; j < G; j += 256)
        rowv[j] = (j == i) ? -1e30f : base[2 * j];
    __syncthreads();

    float m = -1e30f;
    for (int j = tid; j < G; j += 256) m = fmaxf(m, rowv[j]);
    red[tid] = m;
    __syncthreads();
    for (int s = 128; s > 0; s >>= 1) {
        if (tid < s) red[tid] = fmaxf(red[tid], red[tid + s]);
        __syncthreads();
    }
    const float mx = red[0];
    __syncthreads();

    float sum = 0.0f;
    for (int j = tid; j < G; j += 256) {
        const float e = expf(rowv[j] - mx);
        rowv[j] = e;
        sum += e;
    }
    red[tid] = sum;
    __syncthreads();
    for (int s = 128; s > 0; s >>= 1) {
        if (tid < s) red[tid] += red[tid + s];
        __syncthreads();
    }
    const float inv = ALPHA / red[0];
    __syncthreads();

    for (int j = tid; j < G; j += 256)
        Asc[(size_t)i * G + j] = rowv[j] * inv;
}

// ---------------- transpose G x G -------------------------------------------
__global__ void transpose_k(const float* __restrict__ in, float* __restrict__ out) {
    __shared__ float t[32][33];
    const int x  = blockIdx.x * 32 + threadIdx.x;
    const int y0 = blockIdx.y * 32;
#pragma unroll
    for (int dy = 0; dy < 32; dy += 8)
        t[threadIdx.y + dy][threadIdx.x] = in[(size_t)(y0 + threadIdx.y + dy) * G + x];
    __syncthreads();
    const int ox = y0 + threadIdx.x;
#pragma unroll
    for (int dy = 0; dy < 32; dy += 8)
        out[(size_t)(blockIdx.x * 32 + threadIdx.y + dy) * G + ox] =
            t[threadIdx.x][threadIdx.y + dy];
}

// ---------------- deinterleave X channels -----------------------------------
__global__ void deinterleave_kernel(const float* __restrict__ pg,
                                    const float* __restrict__ gg,
                                    float* __restrict__ X2) {
    const size_t total = (size_t)PG * G;
    for (size_t idx = (size_t)blockIdx.x * blockDim.x + threadIdx.x;
         idx < total; idx += (size_t)gridDim.x * blockDim.x) {
        const int i = (int)(idx / G);
        const int k = (int)(idx % G);
        const float* src = (i < P) ? (pg + ((size_t)i * G + k) * 2)
                                   : (gg + ((size_t)(i - P) * G + k) * 2);
        float2 v = *reinterpret_cast<const float2*>(src);
        X2[idx] = v.x;
        X2[(size_t)PG * G + idx] = v.y;
    }
}

// ---------------- launcher ---------------------------------------------------
extern "C" void kernel_launch(void* const* d_in, const int* in_sizes, int n_in,
                              void* d_out, int out_size) {
    const float* pg = (const float*)d_in[0];
    const float* gg = (const float*)d_in[1];
    if (in_sizes[0] == G * G * 2) { const float* t = pg; pg = gg; gg = t; }

    float *Asc, *AscT, *Wa, *Wb, *R, *X2;
    cudaGetSymbolAddress((void**)&Asc,  g_Asc);
    cudaGetSymbolAddress((void**)&AscT, g_AscT);
    cudaGetSymbolAddress((void**)&Wa,   g_Wa);
    cudaGetSymbolAddress((void**)&Wb,   g_Wb);
    cudaGetSymbolAddress((void**)&R,    g_R);
    cudaGetSymbolAddress((void**)&X2,   g_X2);
    float* out = (float*)d_out;

    cudaFuncSetAttribute(gemm_mma<0>, cudaFuncAttributeMaxDynamicSharedMemorySize, SMEM_DYN);
    cudaFuncSetAttribute(gemm_mma<1>, cudaFuncAttributeMaxDynamicSharedMemorySize, SMEM_DYN);

    // 1. Asc = alpha*softmax, X2 = deinterleaved inputs, AscT = Asc^T (= W1)
    softmax_rows_kernel<<<G, 256>>>(gg, Asc);
    deinterleave_kernel<<<2048, 256>>>(pg, gg, X2);
    transpose_k<<<dim3(G / 32, G / 32), dim3(32, 8)>>>(Asc, AscT);

    // 2. Horner chain on W = R^T:  W_{k+1} = W_k . Asc^T + AscT  (2 steps ->
    //    R = alpha*A + alpha^2*A^2 + alpha^3*A^3; truncation ~1.6e-6 abs)
    dim3 gh(G / TN, G / TM);                        // (24, 24)
    gemm_mma<0><<<gh, 256, SMEM_DYN>>>(AscT, Asc, AscT, Wa);  // W2
    gemm_mma<0><<<gh, 256, SMEM_DYN>>>(Wa,   Asc, AscT, Wb);  // W3

    // 3. R = W3^T
    transpose_k<<<dim3(G / 32, G / 32), dim3(32, 8)>>>(Wb, R);

    // 4. out = 0.9 * (X + X @ R^T), channels re-interleaved in epilogue
    dim3 gf(G / TN, M2 / TM);                       // (24, 64)
    gemm_mma<1><<<gf, 256, SMEM_DYN>>>(X2, R, X2, out);
}

// round 5
// speedup vs baseline: 7.7270x; 1.2404x over previous
#include <cuda_runtime.h>
#include <cuda_bf16.h>
#include <math.h>
#include <stdint.h>

#define G 3072
#define P 1024
#define PG 4096          // rows per channel of X
#define M2 8192          // 2 channels stacked
#define ALPHA 0.1f

// ---------------- scratch (device globals; no allocation in kernel_launch) --
__device__ float g_Asc [(size_t)G * G];   // alpha * softmax(scores), row-major
__device__ float g_AscT[(size_t)G * G];   // transpose of Asc (= W1)
__device__ float g_Wa  [(size_t)G * G];
__device__ float g_R   [(size_t)G * G];   // R = W_final^T
__device__ float g_X2  [(size_t)M2 * G];  // deinterleaved X: ch0 rows, then ch1

// ---------------- PTX helpers (all generic sm_100 compatible) ---------------
__device__ __forceinline__ uint32_t smem_u32(const void* p) {
    uint32_t a;
    asm("{ .reg .u64 t; cvta.to.shared.u64 t, %1; cvt.u32.u64 %0, t; }"
        : "=r"(a) : "l"(p));
    return a;
}
__device__ __forceinline__ void cp_async16(uint32_t dst, const void* src) {
    asm volatile("cp.async.cg.shared.global [%0], [%1], 16;" :: "r"(dst), "l"(src));
}
#define CP_COMMIT() asm volatile("cp.async.commit_group;" ::: "memory")
#define CP_WAIT(n)  asm volatile("cp.async.wait_group %0;" :: "n"(n) : "memory")

__device__ __forceinline__ void ldsm_x4(uint32_t* r, uint32_t addr) {
    asm volatile("ldmatrix.sync.aligned.m8n8.x4.shared.b16 {%0,%1,%2,%3}, [%4];"
                 : "=r"(r[0]), "=r"(r[1]), "=r"(r[2]), "=r"(r[3]) : "r"(addr));
}
__device__ __forceinline__ void mma_tf32(float* c, const uint32_t* a, const uint32_t* b) {
    asm volatile(
        "mma.sync.aligned.m16n8k8.row.col.f32.tf32.tf32.f32 "
        "{%0,%1,%2,%3}, {%4,%5,%6,%7}, {%8,%9}, {%0,%1,%2,%3};"
        : "+f"(c[0]), "+f"(c[1]), "+f"(c[2]), "+f"(c[3])
        : "r"(a[0]), "r"(a[1]), "r"(a[2]), "r"(a[3]), "r"(b[0]), "r"(b[1]));
}

// ---------------- GEMM: D[128x128] = A[128,K] . B[128,K]^T ------------------
//   MODE 0: Cout = D + Add                              (Horner step)
//   MODE 1: out[(ii*G+col)*2+c] = 0.9*(Add + D)          (final, interleave)
#define TM 128
#define TN 128
#define KCH 32
#define STAGES 3
#define ATILE_B (TM * KCH * 4)              // 16384
#define STAGE_BYTES (2 * ATILE_B)           // 32768
#define NCHUNK (G / KCH)                    // 96
#define SMEM_DYN (STAGES * STAGE_BYTES)     // 98304

template <int MODE>
__global__ __launch_bounds__(256, 2)
void gemm_mma(const float* __restrict__ Aop, const float* __restrict__ Bop,
              const float* __restrict__ Add, float* __restrict__ Cout) {
    extern __shared__ char smem_raw[];
    const uint32_t sbase = smem_u32(smem_raw);

    const int tid  = threadIdx.x;
    const int lane = tid & 31;
    const int wid  = tid >> 5;
    const int wm   = wid & 3;        // 4 warps along M -> 32 rows each
    const int wn   = wid >> 2;       // 2 warps along N -> 64 cols each
    const int row0 = blockIdx.y * TM;
    const int col0 = blockIdx.x * TN;

    const float* arow = Aop + (size_t)row0 * G;
    const float* brow = Bop + (size_t)col0 * G;

    // smem layout per operand tile: [128 rows][32 f32] = 128B rows, swizzle:
    //   off(r, byte) = r*128 + (byte ^ ((r&7)<<4))
    const int ar    = lane & 15;                 // row within m16 tile
    const int abyte = (lane >> 4) << 4;          // 0 or 16
    const uint32_t amask = (uint32_t)((ar & 7) << 4);
    const uint32_t aoff0 = (uint32_t)((wm * 32 + ar) * 128);
    const uint32_t aoff1 = aoff0 + 16 * 128;
    const int brl   = (lane & 7) | (((lane >> 4) & 1) << 3);
    const int bbyte = ((lane >> 3) & 1) << 4;
    const uint32_t bmask = (uint32_t)((lane & 7) << 4);
    uint32_t boff[4];
#pragma unroll
    for (int ntp = 0; ntp < 4; ntp++)
        boff[ntp] = (uint32_t)((wn * 64 + ntp * 16 + brl) * 128);

    float acc[2][8][4] = {};

    auto load_stage = [&](int stage, int k0) {
        const uint32_t sA = sbase + stage * STAGE_BYTES;
        const uint32_t sB = sA + ATILE_B;
#pragma unroll
        for (int l = 0; l < 4; l++) {
            const int q = tid + (l << 8);
            const int r = q >> 3, sg = q & 7;
            cp_async16(sA + (uint32_t)(r * 128 + ((sg * 16) ^ ((r & 7) << 4))),
                       arow + (size_t)r * G + k0 + sg * 4);
        }
#pragma unroll
        for (int l = 0; l < 4; l++) {
            const int q = tid + (l << 8);
            const int r = q >> 3, sg = q & 7;
            cp_async16(sB + (uint32_t)(r * 128 + ((sg * 16) ^ ((r & 7) << 4))),
                       brow + (size_t)r * G + k0 + sg * 4);
        }
        CP_COMMIT();
    };

    // prologue: STAGES-1 stages in flight
    load_stage(0, 0);
    load_stage(1, KCH);

    for (int ch = 0; ch < NCHUNK; ch++) {
        CP_WAIT(STAGES - 2);
        __syncthreads();
        // Safe to refill slot (ch-1)%STAGES: every thread finished reading it
        // before this barrier (single barrier per iteration, 3-stage ring).
        if (ch + STAGES - 1 < NCHUNK)
            load_stage((ch + STAGES - 1) % STAGES, (ch + STAGES - 1) * KCH);
        else
            CP_COMMIT();   // empty group keeps wait_group accounting uniform

        const uint32_t sA = sbase + (ch % STAGES) * STAGE_BYTES;
        const uint32_t sB = sA + ATILE_B;
#pragma unroll
        for (int ks = 0; ks < 4; ks++) {
            const uint32_t kb = (uint32_t)(ks * 32);
            uint32_t a0[4], a1[4];
            ldsm_x4(a0, sA + aoff0 + ((kb + abyte) ^ amask));
            ldsm_x4(a1, sA + aoff1 + ((kb + abyte) ^ amask));
            uint32_t b[4][4];
#pragma unroll
            for (int ntp = 0; ntp < 4; ntp++)
                ldsm_x4(b[ntp], sB + boff[ntp] + ((kb + bbyte) ^ bmask));
#pragma unroll
            for (int nt = 0; nt < 8; nt++) {
                const uint32_t* bp = &b[nt >> 1][(nt & 1) * 2];
                mma_tf32(acc[0][nt], a0, bp);
                mma_tf32(acc[1][nt], a1, bp);
            }
        }
    }

    // ---------------- epilogue ------------------------------------------------
    const int rbase = lane >> 2;            // 0..7
    const int cbase = (lane & 3) * 2;       // 0,2,4,6
#pragma unroll
    for (int mt = 0; mt < 2; mt++) {
#pragma unroll
        for (int nt = 0; nt < 8; nt++) {
            const int grow = row0 + wm * 32 + mt * 16 + rbase;
            const int gcol = col0 + wn * 64 + nt * 8 + cbase;
#pragma unroll
            for (int h = 0; h < 2; h++) {     // h=0 -> rows r, h=1 -> r+8
                const int gr = grow + h * 8;
                const float v0 = acc[mt][nt][h * 2 + 0];
                const float v1 = acc[mt][nt][h * 2 + 1];
                if (MODE == 0) {
                    const size_t i0 = (size_t)gr * G + gcol;
                    float2 ad = *reinterpret_cast<const float2*>(Add + i0);
                    float2 o;
                    o.x = v0 + ad.x;
                    o.y = v1 + ad.y;
                    *reinterpret_cast<float2*>(Cout + i0) = o;
                } else {
                    const int c  = gr >> 12;           // channel
                    const int ii = gr & (PG - 1);
                    float2 x = *reinterpret_cast<const float2*>(
                        Add + (size_t)gr * G + gcol);
                    float* ob = Cout + ((size_t)ii * G + gcol) * 2 + c;
                    ob[0] = 0.9f * (x.x + v0);
                    ob[2] = 0.9f * (x.y + v1);
                }
            }
        }
    }
}

// ---------------- softmax: Asc = alpha * softmax(gg[:,:,1], -inf diag) -----
__global__ void softmax_rows_kernel(const float* __restrict__ gg,
                                    float* __restrict__ Asc) {
    const int i   = blockIdx.x;
    const int tid = threadIdx.x;
    const float* base = gg + (size_t)i * (2 * G) + 1;

    __shared__ float rowv[G];
    __shared__ float red[256];

    for (int j = tid; j < G; j += 256)
        rowv[j] = (j == i) ? -1e30f : base[2 * j];
    __syncthreads();

    float m = -1e30f;
    for (int j = tid; j < G; j += 256) m = fmaxf(m, rowv[j]);
    red[tid] = m;
    __syncthreads();
    for (int s = 128; s > 0; s >>= 1) {
        if (tid < s) red[tid] = fmaxf(red[tid], red[tid + s]);
        __syncthreads();
    }
    const float mx = red[0];
    __syncthreads();

    float sum = 0.0f;
    for (int j = tid; j < G; j += 256) {
        const float e = expf(rowv[j] - mx);
        rowv[j] = e;
        sum += e;
    }
    red[tid] = sum;
    __syncthreads();
    for (int s = 128; s > 0; s >>= 1) {
        if (tid < s) red[tid] += red[tid + s];
        __syncthreads();
    }
    const float inv = ALPHA / red[0];
    __syncthreads();

    for (int j = tid; j < G; j += 256)
        Asc[(size_t)i * G + j] = rowv[j] * inv;
}

// ---------------- transpose G x G -------------------------------------------
__global__ void transpose_k(const float* __restrict__ in, float* __restrict__ out) {
    __shared__ float t[32][33];
    const int x  = blockIdx.x * 32 + threadIdx.x;
    const int y0 = blockIdx.y * 32;
#pragma unroll
    for (int dy = 0; dy < 32; dy += 8)
        t[threadIdx.y + dy][threadIdx.x] = in[(size_t)(y0 + threadIdx.y + dy) * G + x];
    __syncthreads();
    const int ox = y0 + threadIdx.x;
#pragma unroll
    for (int dy = 0; dy < 32; dy += 8)
        out[(size_t)(blockIdx.x * 32 + threadIdx.y + dy) * G + ox] =
            t[threadIdx.x][threadIdx.y + dy];
}

// ---------------- deinterleave X channels -----------------------------------
__global__ void deinterleave_kernel(const float* __restrict__ pg,
                                    const float* __restrict__ gg,
                                    float* __restrict__ X2) {
    const size_t total = (size_t)PG * G;
    for (size_t idx = (size_t)blockIdx.x * blockDim.x + threadIdx.x;
         idx < total; idx += (size_t)gridDim.x * blockDim.x) {
        const int i = (int)(idx / G);
        const int k = (int)(idx % G);
        const float* src = (i < P) ? (pg + ((size_t)i * G + k) * 2)
                                   : (gg + ((size_t)(i - P) * G + k) * 2);
        float2 v = *reinterpret_cast<const float2*>(src);
        X2[idx] = v.x;
        X2[(size_t)PG * G + idx] = v.y;
    }
}

// ---------------- launcher ---------------------------------------------------
extern "C" void kernel_launch(void* const* d_in, const int* in_sizes, int n_in,
                              void* d_out, int out_size) {
    const float* pg = (const float*)d_in[0];
    const float* gg = (const float*)d_in[1];
    if (in_sizes[0] == G * G * 2) { const float* t = pg; pg = gg; gg = t; }

    float *Asc, *AscT, *Wa, *R, *X2;
    cudaGetSymbolAddress((void**)&Asc,  g_Asc);
    cudaGetSymbolAddress((void**)&AscT, g_AscT);
    cudaGetSymbolAddress((void**)&Wa,   g_Wa);
    cudaGetSymbolAddress((void**)&R,    g_R);
    cudaGetSymbolAddress((void**)&X2,   g_X2);
    float* out = (float*)d_out;

    cudaFuncSetAttribute(gemm_mma<0>, cudaFuncAttributeMaxDynamicSharedMemorySize, SMEM_DYN);
    cudaFuncSetAttribute(gemm_mma<1>, cudaFuncAttributeMaxDynamicSharedMemorySize, SMEM_DYN);

    // 1. Asc = alpha*softmax, X2 = deinterleaved inputs, AscT = Asc^T (= W1)
    softmax_rows_kernel<<<G, 256>>>(gg, Asc);
    deinterleave_kernel<<<2048, 256>>>(pg, gg, X2);
    transpose_k<<<dim3(G / 32, G / 32), dim3(32, 8)>>>(Asc, AscT);

    // 2. Single Horner step: W = AscT . Asc^T + AscT = (alpha*A + alpha^2*A^2)^T
    //    Truncation (alpha^3 term dropped) ~1.8e-5 norm-relative — 45x margin.
    dim3 gh(G / TN, G / TM);                        // (24, 24)
    gemm_mma<0><<<gh, 256, SMEM_DYN>>>(AscT, Asc, AscT, Wa);

    // 3. R = W^T
    transpose_k<<<dim3(G / 32, G / 32), dim3(32, 8)>>>(Wa, R);

    // 4. out = 0.9 * (X + X @ R^T), channels re-interleaved in epilogue
    dim3 gf(G / TN, M2 / TM);                       // (24, 64)
    gemm_mma<1><<<gf, 256, SMEM_DYN>>>(X2, R, X2, out);
}

// round 6
// speedup vs baseline: 13.4404x; 1.7394x over previous
#include <cuda_runtime.h>
#include <cuda_bf16.h>
#include <math.h>
#include <stdint.h>

#define G 3072
#define P 1024
#define PG 4096          // rows per channel of X
#define M2 8192          // 2 channels stacked
#define ALPHA 0.1f

// ---------------- scratch (device globals; no allocation in kernel_launch) --
__device__ float         g_Asc  [(size_t)G * G];   // alpha*softmax, fp32 (Add path)
__device__ __nv_bfloat16 g_Ascb [(size_t)G * G];   // bf16 twin (A-operand)
__device__ __nv_bfloat16 g_AscTb[(size_t)G * G];   // bf16 transpose (B-operand)
__device__ __nv_bfloat16 g_Rb   [(size_t)G * G];   // R = Asc^2 + Asc, bf16
__device__ float         g_X2   [(size_t)M2 * G];  // deinterleaved X, fp32 (Add)
__device__ __nv_bfloat16 g_X2b  [(size_t)M2 * G];  // bf16 twin (A-operand)

// ---------------- PTX helpers (generic sm_100 compatible) -------------------
__device__ __forceinline__ uint32_t smem_u32(const void* p) {
    uint32_t a;
    asm("{ .reg .u64 t; cvta.to.shared.u64 t, %1; cvt.u32.u64 %0, t; }"
        : "=r"(a) : "l"(p));
    return a;
}
__device__ __forceinline__ void cp_async16(uint32_t dst, const void* src) {
    asm volatile("cp.async.cg.shared.global [%0], [%1], 16;" :: "r"(dst), "l"(src));
}
#define CP_COMMIT() asm volatile("cp.async.commit_group;" ::: "memory")
#define CP_WAIT(n)  asm volatile("cp.async.wait_group %0;" :: "n"(n) : "memory")

__device__ __forceinline__ void ldsm_x4(uint32_t* r, uint32_t addr) {
    asm volatile("ldmatrix.sync.aligned.m8n8.x4.shared.b16 {%0,%1,%2,%3}, [%4];"
                 : "=r"(r[0]), "=r"(r[1]), "=r"(r[2]), "=r"(r[3]) : "r"(addr));
}
__device__ __forceinline__ void mma_bf16(float* c, const uint32_t* a, const uint32_t* b) {
    asm volatile(
        "mma.sync.aligned.m16n8k16.row.col.f32.bf16.bf16.f32 "
        "{%0,%1,%2,%3}, {%4,%5,%6,%7}, {%8,%9}, {%0,%1,%2,%3};"
        : "+f"(c[0]), "+f"(c[1]), "+f"(c[2]), "+f"(c[3])
        : "r"(a[0]), "r"(a[1]), "r"(a[2]), "r"(a[3]), "r"(b[0]), "r"(b[1]));
}

// ---------------- GEMM: D[128x128] = A[128,K] . B[128,K]^T  (bf16 x bf16) ---
//   MODE 0: Rb = bf16(D + Add)                          (R = Asc^2 + Asc)
//   MODE 1: out[(ii*G+col)*2+c] = 0.9*(Add + D)          (final, interleave)
#define TM 128
#define TN 128
#define KCH 64                               // 64 bf16 = 128B rows
#define STAGES 3
#define ATILE_B (TM * KCH * 2)               // 16384
#define STAGE_BYTES (2 * ATILE_B)            // 32768
#define NCHUNK (G / KCH)                     // 48
#define SMEM_DYN (STAGES * STAGE_BYTES)      // 98304

template <int MODE>
__global__ __launch_bounds__(256, 2)
void gemm_mma(const __nv_bfloat16* __restrict__ Aop,
              const __nv_bfloat16* __restrict__ Bop,
              const float* __restrict__ Add, void* __restrict__ CoutV) {
    extern __shared__ char smem_raw[];
    const uint32_t sbase = smem_u32(smem_raw);

    const int tid  = threadIdx.x;
    const int lane = tid & 31;
    const int wid  = tid >> 5;
    const int wm   = wid & 3;        // 4 warps along M -> 32 rows each
    const int wn   = wid >> 2;       // 2 warps along N -> 64 cols each
    const int row0 = blockIdx.y * TM;
    const int col0 = blockIdx.x * TN;

    const __nv_bfloat16* arow = Aop + (size_t)row0 * G;
    const __nv_bfloat16* brow = Bop + (size_t)col0 * G;

    // smem per operand tile: [128 rows][64 bf16] = 128B rows, swizzle:
    //   off(r, byte) = r*128 + (byte ^ ((r&7)<<4))
    // A fragment (m16k16 bf16, ldmatrix x4): identical address pattern to the
    // validated tf32 k8 version (16B segment = k8 halves vs k4 floats).
    const int ar    = lane & 15;
    const int abyte = (lane >> 4) << 4;
    const uint32_t amask = (uint32_t)((ar & 7) << 4);
    const uint32_t aoff0 = (uint32_t)((wm * 32 + ar) * 128);
    const uint32_t aoff1 = aoff0 + 16 * 128;
    const int brl   = (lane & 7) | (((lane >> 4) & 1) << 3);
    const int bbyte = ((lane >> 3) & 1) << 4;
    const uint32_t bmask = (uint32_t)((lane & 7) << 4);
    uint32_t boff[4];
#pragma unroll
    for (int ntp = 0; ntp < 4; ntp++)
        boff[ntp] = (uint32_t)((wn * 64 + ntp * 16 + brl) * 128);

    float acc[2][8][4] = {};

    auto load_stage = [&](int stage, int k0) {
        const uint32_t sA = sbase + stage * STAGE_BYTES;
        const uint32_t sB = sA + ATILE_B;
#pragma unroll
        for (int l = 0; l < 4; l++) {
            const int q = tid + (l << 8);
            const int r = q >> 3, sg = q & 7;
            cp_async16(sA + (uint32_t)(r * 128 + ((sg * 16) ^ ((r & 7) << 4))),
                       arow + (size_t)r * G + k0 + sg * 8);
        }
#pragma unroll
        for (int l = 0; l < 4; l++) {
            const int q = tid + (l << 8);
            const int r = q >> 3, sg = q & 7;
            cp_async16(sB + (uint32_t)(r * 128 + ((sg * 16) ^ ((r & 7) << 4))),
                       brow + (size_t)r * G + k0 + sg * 8);
        }
        CP_COMMIT();
    };

    load_stage(0, 0);
    load_stage(1, KCH);

    for (int ch = 0; ch < NCHUNK; ch++) {
        CP_WAIT(STAGES - 2);
        __syncthreads();
        if (ch + STAGES - 1 < NCHUNK)
            load_stage((ch + STAGES - 1) % STAGES, (ch + STAGES - 1) * KCH);
        else
            CP_COMMIT();   // keep wait_group accounting uniform

        const uint32_t sA = sbase + (ch % STAGES) * STAGE_BYTES;
        const uint32_t sB = sA + ATILE_B;
#pragma unroll
        for (int ks = 0; ks < 4; ks++) {       // 4 x k16 steps = k64 chunk
            const uint32_t kb = (uint32_t)(ks * 32);
            uint32_t a0[4], a1[4];
            ldsm_x4(a0, sA + aoff0 + ((kb + abyte) ^ amask));
            ldsm_x4(a1, sA + aoff1 + ((kb + abyte) ^ amask));
            uint32_t b[4][4];
#pragma unroll
            for (int ntp = 0; ntp < 4; ntp++)
                ldsm_x4(b[ntp], sB + boff[ntp] + ((kb + bbyte) ^ bmask));
#pragma unroll
            for (int nt = 0; nt < 8; nt++) {
                const uint32_t* bp = &b[nt >> 1][(nt & 1) * 2];
                mma_bf16(acc[0][nt], a0, bp);
                mma_bf16(acc[1][nt], a1, bp);
            }
        }
    }

    // ---------------- epilogue ------------------------------------------------
    const int rbase = lane >> 2;            // 0..7
    const int cbase = (lane & 3) * 2;       // 0,2,4,6
#pragma unroll
    for (int mt = 0; mt < 2; mt++) {
#pragma unroll
        for (int nt = 0; nt < 8; nt++) {
            const int grow = row0 + wm * 32 + mt * 16 + rbase;
            const int gcol = col0 + wn * 64 + nt * 8 + cbase;
#pragma unroll
            for (int h = 0; h < 2; h++) {
                const int gr = grow + h * 8;
                const float v0 = acc[mt][nt][h * 2 + 0];
                const float v1 = acc[mt][nt][h * 2 + 1];
                if (MODE == 0) {
                    const size_t i0 = (size_t)gr * G + gcol;
                    float2 ad = *reinterpret_cast<const float2*>(Add + i0);
                    __nv_bfloat162 o = __float22bfloat162_rn(
                        make_float2(v0 + ad.x, v1 + ad.y));
                    *reinterpret_cast<__nv_bfloat162*>(
                        (__nv_bfloat16*)CoutV + i0) = o;
                } else {
                    const int c  = gr >> 12;           // channel
                    const int ii = gr & (PG - 1);
                    float2 x = *reinterpret_cast<const float2*>(
                        Add + (size_t)gr * G + gcol);
                    float* ob = (float*)CoutV + ((size_t)ii * G + gcol) * 2 + c;
                    ob[0] = 0.9f * (x.x + v0);
                    ob[2] = 0.9f * (x.y + v1);
                }
            }
        }
    }
}

// ---------------- softmax: Asc = alpha * softmax(gg[:,:,1], -inf diag) -----
__global__ void softmax_rows_kernel(const float* __restrict__ gg,
                                    float* __restrict__ Asc,
                                    __nv_bfloat16* __restrict__ Ascb) {
    const int i   = blockIdx.x;
    const int tid = threadIdx.x;
    const float* base = gg + (size_t)i * (2 * G) + 1;

    __shared__ float rowv[G];
    __shared__ float red[256];

    for (int j = tid; j < G; j += 256)
        rowv[j] = (j == i) ? -1e30f : base[2 * j];
    __syncthreads();

    float m = -1e30f;
    for (int j = tid; j < G; j += 256) m = fmaxf(m, rowv[j]);
    red[tid] = m;
    __syncthreads();
    for (int s = 128; s > 0; s >>= 1) {
        if (tid < s) red[tid] = fmaxf(red[tid], red[tid + s]);
        __syncthreads();
    }
    const float mx = red[0];
    __syncthreads();

    float sum = 0.0f;
    for (int j = tid; j < G; j += 256) {
        const float e = expf(rowv[j] - mx);
        rowv[j] = e;
        sum += e;
    }
    red[tid] = sum;
    __syncthreads();
    for (int s = 128; s > 0; s >>= 1) {
        if (tid < s) red[tid] += red[tid + s];
        __syncthreads();
    }
    const float inv = ALPHA / red[0];
    __syncthreads();

    for (int j = tid; j < G; j += 256) {
        const float v = rowv[j] * inv;
        Asc[(size_t)i * G + j]  = v;
        Ascb[(size_t)i * G + j] = __float2bfloat16(v);
    }
}

// ---------------- transpose G x G: fp32 in -> bf16 out ----------------------
__global__ void transpose_b_k(const float* __restrict__ in,
                              __nv_bfloat16* __restrict__ out) {
    __shared__ float t[32][33];
    const int x  = blockIdx.x * 32 + threadIdx.x;
    const int y0 = blockIdx.y * 32;
#pragma unroll
    for (int dy = 0; dy < 32; dy += 8)
        t[threadIdx.y + dy][threadIdx.x] = in[(size_t)(y0 + threadIdx.y + dy) * G + x];
    __syncthreads();
    const int ox = y0 + threadIdx.x;
#pragma unroll
    for (int dy = 0; dy < 32; dy += 8)
        out[(size_t)(blockIdx.x * 32 + threadIdx.y + dy) * G + ox] =
            __float2bfloat16(t[threadIdx.x][threadIdx.y + dy]);
}

// ---------------- deinterleave X channels (fp32 + bf16 twins) ---------------
__global__ void deinterleave_kernel(const float* __restrict__ pg,
                                    const float* __restrict__ gg,
                                    float* __restrict__ X2,
                                    __nv_bfloat16* __restrict__ X2b) {
    const size_t total = (size_t)PG * G;
    for (size_t idx = (size_t)blockIdx.x * blockDim.x + threadIdx.x;
         idx < total; idx += (size_t)gridDim.x * blockDim.x) {
        const int i = (int)(idx / G);
        const int k = (int)(idx % G);
        const float* src = (i < P) ? (pg + ((size_t)i * G + k) * 2)
                                   : (gg + ((size_t)(i - P) * G + k) * 2);
        float2 v = *reinterpret_cast<const float2*>(src);
        X2[idx] = v.x;
        X2[(size_t)PG * G + idx] = v.y;
        X2b[idx] = __float2bfloat16(v.x);
        X2b[(size_t)PG * G + idx] = __float2bfloat16(v.y);
    }
}

// ---------------- launcher ---------------------------------------------------
extern "C" void kernel_launch(void* const* d_in, const int* in_sizes, int n_in,
                              void* d_out, int out_size) {
    const float* pg = (const float*)d_in[0];
    const float* gg = (const float*)d_in[1];
    if (in_sizes[0] == G * G * 2) { const float* t = pg; pg = gg; gg = t; }

    float *Asc, *X2;
    __nv_bfloat16 *Ascb, *AscTb, *Rb, *X2b;
    cudaGetSymbolAddress((void**)&Asc,   g_Asc);
    cudaGetSymbolAddress((void**)&Ascb,  g_Ascb);
    cudaGetSymbolAddress((void**)&AscTb, g_AscTb);
    cudaGetSymbolAddress((void**)&Rb,    g_Rb);
    cudaGetSymbolAddress((void**)&X2,    g_X2);
    cudaGetSymbolAddress((void**)&X2b,   g_X2b);
    float* out = (float*)d_out;

    cudaFuncSetAttribute(gemm_mma<0>, cudaFuncAttributeMaxDynamicSharedMemorySize, SMEM_DYN);
    cudaFuncSetAttribute(gemm_mma<1>, cudaFuncAttributeMaxDynamicSharedMemorySize, SMEM_DYN);

    // 1. Asc (+bf16 twin), X2 (+bf16 twin), AscTb = Asc^T in bf16
    softmax_rows_kernel<<<G, 256>>>(gg, Asc, Ascb);
    deinterleave_kernel<<<2048, 256>>>(pg, gg, X2, X2b);
    transpose_b_k<<<dim3(G / 32, G / 32), dim3(32, 8)>>>(Asc, AscTb);

    // 2. R = Asc^2 + Asc  (row-major directly: D[m,n] = sum_k Asc[m,k]Asc[k,n])
    dim3 gh(G / TN, G / TM);                        // (24, 24)
    gemm_mma<0><<<gh, 256, SMEM_DYN>>>(Ascb, AscTb, Asc, Rb);

    // 3. out = 0.9 * (X + X @ R^T), channels re-interleaved in epilogue
    dim3 gf(G / TN, M2 / TM);                       // (24, 64)
    gemm_mma<1><<<gf, 256, SMEM_DYN>>>(X2b, Rb, X2, out);
}